// round 5
// baseline (speedup 1.0000x reference)
#include <cuda_runtime.h>
#include <math.h>
#include <stdint.h>

#define BATCH 2
#define SEQ   2048
#define DMODEL 2048
#define NHEAD 16
#define DHEAD 128
#define D3    (3*DMODEL)
#define KDIM  2048

// Scratch (device globals — no allocation allowed)
__device__ float g_qkv[(size_t)BATCH * SEQ * D3];        // [B,S,3D]
__device__ float g_attn[(size_t)BATCH * SEQ * DMODEL];   // [B,S,D]
__device__ float g_cos[SEQ * 64];
__device__ float g_sin[SEQ * 64];

__device__ __forceinline__ uint32_t f2tf32(float x) {
    uint32_t r;
    asm("cvt.rna.tf32.f32 %0, %1;" : "=r"(r) : "f"(x));
    return r;
}

__device__ __forceinline__ void mma_tf32(float& d0, float& d1, float& d2, float& d3,
                                         uint32_t a0, uint32_t a1, uint32_t a2, uint32_t a3,
                                         uint32_t b0, uint32_t b1) {
    asm volatile(
        "mma.sync.aligned.m16n8k8.row.col.f32.tf32.tf32.f32 "
        "{%0,%1,%2,%3}, {%4,%5,%6,%7}, {%8,%9}, {%0,%1,%2,%3};"
        : "+f"(d0), "+f"(d1), "+f"(d2), "+f"(d3)
        : "r"(a0), "r"(a1), "r"(a2), "r"(a3), "r"(b0), "r"(b1));
}

// ===========================================================================
// mma.sync tf32 GEMM: C[M,N] = A[M,2048] @ W[2048,N] + bias[N]
// CTA tile 128x128, BK=32, 256 threads (8 warps: 4(m) x 2(n), warp tile 32x64).
// SMEM holds tiles in fragment order (lane-register order) -> conflict-free.
// 2 CTAs/SM for latency overlap.
// ===========================================================================
#define BK 32
#define NT (KDIM / BK)
#define STG_BYTES 32768      // 16KB A frags + 16KB B frags
#define GEMM_SMEM (2 * STG_BYTES)

__global__ void __launch_bounds__(256, 2)
mma_gemm_kernel(const float* __restrict__ A, const float* __restrict__ W,
                const float* __restrict__ bias, float* __restrict__ C, int N) {
    extern __shared__ char smem[];

    const int tid  = threadIdx.x;
    const int lane = tid & 31;
    const int warp = tid >> 5;
    const int wm   = warp >> 1;          // 0..3
    const int wn   = warp & 1;           // 0..1
    const int grp  = lane >> 2;          // 0..7
    const int tig  = lane & 3;           // 0..3
    const int brow = blockIdx.y;
    const int bcol = blockIdx.x;

    float4 bufA[4];
    float2 bufB[8];

    auto ldg_chunk = [&](int j) {
        int k0 = j * BK;
#pragma unroll
        for (int i = 0; i < 4; i++) {
            int f = tid + i * 256;
            int lf = f & 31, ks = (f >> 5) & 3, mt = f >> 7;
            int g = lf >> 2, t = lf & 3;
            const float* ap = A + (size_t)(brow * 128 + mt * 16 + g) * KDIM
                                + k0 + ks * 8 + t;
            bufA[i].x = ap[0];
            bufA[i].y = ap[8 * KDIM];
            bufA[i].z = ap[4];
            bufA[i].w = ap[8 * KDIM + 4];
        }
#pragma unroll
        for (int i = 0; i < 8; i++) {
            int f = tid + i * 256;
            int lf = f & 31, ks = (f >> 5) & 3, nt = f >> 7;
            int g = lf >> 2, t = lf & 3;
            const float* bp = W + (size_t)(k0 + ks * 8 + t) * N
                                + bcol * 128 + nt * 8 + g;
            bufB[i].x = bp[0];
            bufB[i].y = bp[4 * (size_t)N];
        }
    };

    auto sts_chunk = [&](int s) {
        char* sa = smem + s * STG_BYTES;
        char* sb = sa + 16384;
#pragma unroll
        for (int i = 0; i < 4; i++) {
            int f = tid + i * 256;
            int lf = f & 31, ks = (f >> 5) & 3, mt = f >> 7;
            uint4 v;
            v.x = f2tf32(bufA[i].x); v.y = f2tf32(bufA[i].y);
            v.z = f2tf32(bufA[i].z); v.w = f2tf32(bufA[i].w);
            *(uint4*)(sa + ((mt * 4 + ks) * 32 + lf) * 16) = v;
        }
#pragma unroll
        for (int i = 0; i < 8; i++) {
            int f = tid + i * 256;
            int lf = f & 31, ks = (f >> 5) & 3, nt = f >> 7;
            uint2 v;
            v.x = f2tf32(bufB[i].x); v.y = f2tf32(bufB[i].y);
            *(uint2*)(sb + ((nt * 4 + ks) * 32 + lf) * 8) = v;
        }
    };

    float acc[2][8][4];
#pragma unroll
    for (int m = 0; m < 2; m++)
#pragma unroll
        for (int n = 0; n < 8; n++)
#pragma unroll
            for (int c = 0; c < 4; c++) acc[m][n][c] = 0.f;

    ldg_chunk(0);
    sts_chunk(0);
    __syncthreads();

    for (int j = 0; j < NT; j++) {
        if (j + 1 < NT) ldg_chunk(j + 1);

        char* sa = smem + (j & 1) * STG_BYTES;
        char* sb = sa + 16384;
#pragma unroll
        for (int ks = 0; ks < 4; ks++) {
            uint4 af[2];
#pragma unroll
            for (int m = 0; m < 2; m++)
                af[m] = *(uint4*)(sa + (((wm * 2 + m) * 4 + ks) * 32 + lane) * 16);
            uint2 bf[8];
#pragma unroll
            for (int n = 0; n < 8; n++)
                bf[n] = *(uint2*)(sb + (((wn * 8 + n) * 4 + ks) * 32 + lane) * 8);
#pragma unroll
            for (int m = 0; m < 2; m++)
#pragma unroll
                for (int n = 0; n < 8; n++)
                    mma_tf32(acc[m][n][0], acc[m][n][1], acc[m][n][2], acc[m][n][3],
                             af[m].x, af[m].y, af[m].z, af[m].w,
                             bf[n].x, bf[n].y);
        }

        if (j + 1 < NT) sts_chunk((j + 1) & 1);
        __syncthreads();
    }

    // Epilogue
#pragma unroll
    for (int m = 0; m < 2; m++) {
        int row0 = brow * 128 + wm * 32 + m * 16 + grp;
#pragma unroll
        for (int n = 0; n < 8; n++) {
            int col = bcol * 128 + wn * 64 + n * 8 + tig * 2;
            float2 bv = *(const float2*)(bias + col);
            float2 o0, o1;
            o0.x = acc[m][n][0] + bv.x; o0.y = acc[m][n][1] + bv.y;
            o1.x = acc[m][n][2] + bv.x; o1.y = acc[m][n][3] + bv.y;
            *(float2*)(C + (size_t)row0 * N + col)       = o0;
            *(float2*)(C + (size_t)(row0 + 8) * N + col) = o1;
        }
    }
}

// ===========================================================================
// RoPE
// ===========================================================================
__global__ void rope_table_kernel() {
    int idx = blockIdx.x * blockDim.x + threadIdx.x;
    if (idx >= SEQ * 64) return;
    int s = idx >> 6;
    int i = idx & 63;
    double theta = exp(-(double)i * log(10000.0) / 64.0);
    float tf = (float)theta;
    float ang = (float)s * tf;
    g_cos[idx] = (float)cos((double)ang);
    g_sin[idx] = (float)sin((double)ang);
}

__global__ void rope_apply_kernel() {
    int idx = blockIdx.x * blockDim.x + threadIdx.x;
    int i = idx & 63;
    int h = (idx >> 6) & (NHEAD - 1);
    int s = (idx >> 10) & (SEQ - 1);
    int b = idx >> 21;
    if (b >= BATCH) return;

    float c  = g_cos[s * 64 + i];
    float sn = g_sin[s * 64 + i];

    size_t base = ((size_t)(b * SEQ + s)) * D3 + h * DHEAD;
    float* q = g_qkv + base;
    float* k = g_qkv + base + DMODEL;

    float q0 = q[i], q1 = q[i + 64];
    q[i]      = c * q0 - sn * q1;
    q[i + 64] = c * q1 + sn * q0;

    float k0 = k[i], k1 = k[i + 64];
    k[i]      = c * k0 - sn * k1;
    k[i + 64] = c * k1 + sn * k0;
}

// ===========================================================================
// Flash attention fp32 — parallel row reductions (4 lanes/row + shfl.bfly),
// SCALE folded into Q load, causal mask applied on the fly.
// ===========================================================================
#define ATT_SMEM_FLOATS (128*65 + 128*65 + 64*128 + 64*65 + 3*64)

__global__ __launch_bounds__(256, 2)
void attn_kernel(const float* __restrict__ qkv, float* __restrict__ out) {
    extern __shared__ float sm[];
    float* Qs = sm;                    // [128][65]  d-major, pre-scaled
    float* Ks = Qs + 128 * 65;         // [128][65]
    float* Vs = Ks + 128 * 65;         // [64][128]
    float* Ps = Vs + 64 * 128;         // [64][65]
    float* sh_m     = Ps + 64 * 65;
    float* sh_alpha = sh_m + 64;
    float* sh_l     = sh_alpha + 64;

    const float SCALE = 0.08838834764831845f;  // 1/sqrt(128)
    const float NEG_BIG = -3.0e38f;

    int qt = blockIdx.x;
    int h  = blockIdx.y;
    int b  = blockIdx.z;
    int tid = threadIdx.x;
    int tx = tid & 15;
    int ty = tid >> 4;
    int rid = tid >> 2;    // row for reduction passes (0..63)
    int rq  = tid & 3;     // 4 lanes per row (consecutive lanes)

    const float* qbase = qkv + ((size_t)(b * SEQ)) * D3 + h * DHEAD;
    const float* kbase = qbase + DMODEL;
    const float* vbase = qbase + 2 * DMODEL;

    int qrow0 = qt * 64;

    // Load Q tile transposed & pre-scaled: Qs[d][r] = SCALE * q
#pragma unroll
    for (int t = 0; t < 8; t++) {
        int lin = tid + t * 256;
        int row = lin >> 5;
        int d0 = (lin & 31) * 4;
        float4 v = *(const float4*)(qbase + (size_t)(qrow0 + row) * D3 + d0);
        Qs[(d0 + 0) * 65 + row] = v.x * SCALE;
        Qs[(d0 + 1) * 65 + row] = v.y * SCALE;
        Qs[(d0 + 2) * 65 + row] = v.z * SCALE;
        Qs[(d0 + 3) * 65 + row] = v.w * SCALE;
    }
    if (tid < 64) { sh_m[tid] = NEG_BIG; sh_l[tid] = 0.f; }

    float O[4][8];
#pragma unroll
    for (int i = 0; i < 4; i++)
#pragma unroll
        for (int j = 0; j < 8; j++) O[i][j] = 0.f;

    for (int kt = 0; kt <= qt; kt++) {
        __syncthreads();

        // Load K transposed + V straight
#pragma unroll
        for (int t = 0; t < 8; t++) {
            int lin = tid + t * 256;
            int row = lin >> 5;
            int d0 = (lin & 31) * 4;
            size_t goff = (size_t)(kt * 64 + row) * D3 + d0;
            float4 kv = *(const float4*)(kbase + goff);
            Ks[(d0 + 0) * 65 + row] = kv.x;
            Ks[(d0 + 1) * 65 + row] = kv.y;
            Ks[(d0 + 2) * 65 + row] = kv.z;
            Ks[(d0 + 3) * 65 + row] = kv.w;
            float4 vv = *(const float4*)(vbase + goff);
            *(float4*)(Vs + row * 128 + d0) = vv;
        }
        __syncthreads();

        // S = Q @ K^T (already scaled via Q)
        float accS[4][4];
#pragma unroll
        for (int i = 0; i < 4; i++)
#pragma unroll
            for (int j = 0; j < 4; j++) accS[i][j] = 0.f;

#pragma unroll 4
        for (int d = 0; d < 128; d++) {
            float qr[4], kr[4];
#pragma unroll
            for (int i = 0; i < 4; i++) qr[i] = Qs[d * 65 + ty * 4 + i];
#pragma unroll
            for (int j = 0; j < 4; j++) kr[j] = Ks[d * 65 + tx * 4 + j];
#pragma unroll
            for (int i = 0; i < 4; i++)
#pragma unroll
                for (int j = 0; j < 4; j++) accS[i][j] += qr[i] * kr[j];
        }
#pragma unroll
        for (int i = 0; i < 4; i++)
#pragma unroll
            for (int j = 0; j < 4; j++)
                Ps[(ty * 4 + i) * 65 + tx * 4 + j] = accS[i][j];
        __syncthreads();

        // Pass A: parallel row max (4 lanes/row, 16 cols each, causal on the fly)
        {
            int limit = (kt == qt) ? rid : 63;
            float mt = NEG_BIG;
#pragma unroll
            for (int c0 = 0; c0 < 16; c0++) {
                int c = rq * 16 + c0;
                float v = Ps[rid * 65 + c];
                if (c <= limit) mt = fmaxf(mt, v);
            }
            mt = fmaxf(mt, __shfl_xor_sync(0xFFFFFFFF, mt, 1));
            mt = fmaxf(mt, __shfl_xor_sync(0xFFFFFFFF, mt, 2));
            if (rq == 0) {
                float mo = sh_m[rid];
                float mn = fmaxf(mo, mt);
                sh_m[rid] = mn;
                sh_alpha[rid] = __expf(mo - mn);
            }
        }
        __syncthreads();

        // Rescale O; exponentiate with causal mask -> Ps holds p (0 if masked)
#pragma unroll
        for (int i = 0; i < 4; i++) {
            float a = sh_alpha[ty * 4 + i];
#pragma unroll
            for (int j = 0; j < 8; j++) O[i][j] *= a;
        }
#pragma unroll
        for (int i = 0; i < 4; i++) {
            int r = ty * 4 + i;
            int limit = (kt == qt) ? r : 63;
            float mn = sh_m[r];
#pragma unroll
            for (int j = 0; j < 4; j++) {
                int c = tx * 4 + j;
                float p = (c <= limit) ? __expf(Ps[r * 65 + c] - mn) : 0.f;
                Ps[r * 65 + c] = p;
            }
        }
        __syncthreads();

        // Pass B: parallel row sum
        {
            float s = 0.f;
#pragma unroll
            for (int c0 = 0; c0 < 16; c0++)
                s += Ps[rid * 65 + rq * 16 + c0];
            s += __shfl_xor_sync(0xFFFFFFFF, s, 1);
            s += __shfl_xor_sync(0xFFFFFFFF, s, 2);
            if (rq == 0)
                sh_l[rid] = sh_l[rid] * sh_alpha[rid] + s;
        }

        // O += P @ V
#pragma unroll 2
        for (int k = 0; k < 64; k++) {
            float pr[4];
#pragma unroll
            for (int i = 0; i < 4; i++) pr[i] = Ps[(ty * 4 + i) * 65 + k];
            float vr[8];
            *(float4*)(vr)     = *(float4*)(Vs + k * 128 + tx * 8);
            *(float4*)(vr + 4) = *(float4*)(Vs + k * 128 + tx * 8 + 4);
#pragma unroll
            for (int i = 0; i < 4; i++)
#pragma unroll
                for (int j = 0; j < 8; j++) O[i][j] += pr[i] * vr[j];
        }
    }
    __syncthreads();

    // Normalize + write
#pragma unroll
    for (int i = 0; i < 4; i++) {
        int r = ty * 4 + i;
        float inv = 1.f / sh_l[r];
        int qg = qrow0 + r;
        float o[8];
#pragma unroll
        for (int j = 0; j < 8; j++) o[j] = O[i][j] * inv;
        float* dst = out + ((size_t)(b * SEQ + qg)) * DMODEL + h * DHEAD + tx * 8;
        *(float4*)(dst)     = *(float4*)(o);
        *(float4*)(dst + 4) = *(float4*)(o + 4);
    }
}

// ===========================================================================
// Launch
// ===========================================================================
extern "C" void kernel_launch(void* const* d_in, const int* in_sizes, int n_in,
                              void* d_out, int out_size) {
    const float* x     = (const float*)d_in[0];
    const float* w_in  = (const float*)d_in[2];
    const float* b_in  = (const float*)d_in[3];
    const float* w_out = (const float*)d_in[4];
    const float* b_out = (const float*)d_in[5];
    float* out = (float*)d_out;

    float* qkv;   cudaGetSymbolAddress((void**)&qkv,  g_qkv);
    float* attn;  cudaGetSymbolAddress((void**)&attn, g_attn);

    cudaFuncSetAttribute(attn_kernel,
                         cudaFuncAttributeMaxDynamicSharedMemorySize,
                         ATT_SMEM_FLOATS * (int)sizeof(float));
    cudaFuncSetAttribute(mma_gemm_kernel,
                         cudaFuncAttributeMaxDynamicSharedMemorySize,
                         GEMM_SMEM);

    // 1. RoPE tables
    rope_table_kernel<<<(SEQ * 64 + 255) / 256, 256>>>();

    // 2. QKV projection (mma.sync tf32)
    mma_gemm_kernel<<<dim3(D3 / 128, (BATCH * SEQ) / 128), 256, GEMM_SMEM>>>(
        x, w_in, b_in, qkv, D3);

    // 3. RoPE in-place on q,k
    rope_apply_kernel<<<(BATCH * SEQ * NHEAD * 64) / 256, 256>>>();

    // 4. Flash attention
    attn_kernel<<<dim3(SEQ / 64, NHEAD, BATCH), 256,
                  ATT_SMEM_FLOATS * sizeof(float)>>>(qkv, attn);

    // 5. Output projection (mma.sync tf32)
    mma_gemm_kernel<<<dim3(DMODEL / 128, (BATCH * SEQ) / 128), 256, GEMM_SMEM>>>(
        attn, w_out, b_out, out, DMODEL);
}

// round 6
// speedup vs baseline: 1.8656x; 1.8656x over previous
#include <cuda_runtime.h>
#include <math.h>
#include <stdint.h>

#define BATCH 2
#define SEQ   2048
#define DMODEL 2048
#define NHEAD 16
#define DHEAD 128
#define D3    (3*DMODEL)
#define KDIM  2048

// Scratch (device globals — no allocation allowed)
__device__ float g_qkv[(size_t)BATCH * SEQ * D3];        // [B,S,3D]
__device__ float g_attn[(size_t)BATCH * SEQ * DMODEL];   // [B,S,D]
__device__ float g_cos[SEQ * 64];
__device__ float g_sin[SEQ * 64];

__device__ __forceinline__ uint32_t f2tf32(float x) {
    uint32_t r;
    asm("cvt.rna.tf32.f32 %0, %1;" : "=r"(r) : "f"(x));
    return r;
}

__device__ __forceinline__ void mma_tf32(float& d0, float& d1, float& d2, float& d3,
                                         uint32_t a0, uint32_t a1, uint32_t a2, uint32_t a3,
                                         uint32_t b0, uint32_t b1) {
    asm volatile(
        "mma.sync.aligned.m16n8k8.row.col.f32.tf32.tf32.f32 "
        "{%0,%1,%2,%3}, {%4,%5,%6,%7}, {%8,%9}, {%0,%1,%2,%3};"
        : "+f"(d0), "+f"(d1), "+f"(d2), "+f"(d3)
        : "r"(a0), "r"(a1), "r"(a2), "r"(a3), "r"(b0), "r"(b1));
}

// ===========================================================================
// mma.sync tf32 GEMM: C[M,N] = A[M,2048] @ W[2048,N] + bias[N]
// CTA tile 128x128, BK=32, 256 threads (8 warps: 4(m) x 2(n), warp 32x64).
// Coalesced LDG.128 -> cvt.rna -> STS.128 into padded plain layouts:
//   A smem [128][AS=36]  (bank = 4*grp + tig  -> conflict-free frag reads)
//   B smem [32][BS=136]  (bank = 8*tig + grp  -> conflict-free frag reads)
// Double-buffered, 1 CTA/SM (168 regs OK).
// ===========================================================================
#define BK 32
#define NT (KDIM / BK)
#define AS 36
#define BS 136
#define A_STG (128 * AS)              // floats
#define B_STG (32 * BS)
#define STG_FLOATS (A_STG + B_STG)    // 4608 + 4352 = 8960 floats = 35840 B
#define GEMM_SMEM (2 * STG_FLOATS * 4)

__global__ void __launch_bounds__(256, 1)
mma_gemm_kernel(const float* __restrict__ A, const float* __restrict__ W,
                const float* __restrict__ bias, float* __restrict__ C, int N) {
    extern __shared__ float smem[];

    const int tid  = threadIdx.x;
    const int lane = tid & 31;
    const int warp = tid >> 5;
    const int wm   = warp >> 1;          // 0..3
    const int wn   = warp & 1;           // 0..1
    const int grp  = lane >> 2;          // 0..7
    const int tig  = lane & 3;           // 0..3
    const int brow = blockIdx.y;
    const int bcol = blockIdx.x;

    // loader indices (constant per thread)
    const int ar  = tid >> 3;            // A row (first of 4, step 32)
    const int ac4 = tid & 7;             // A col/4
    const int bk  = tid >> 5;            // B k row (first of 4, step 8)
    const int bc4 = tid & 31;            // B col/4

    const float* Ag = A + (size_t)(brow * 128 + ar) * KDIM + ac4 * 4;
    const float* Wg = W + (size_t)bk * N + bcol * 128 + bc4 * 4;

    float4 bufA[4], bufB[4];

    auto ldg_chunk = [&](int j) {
        int k0 = j * BK;
#pragma unroll
        for (int i = 0; i < 4; i++)
            bufA[i] = *(const float4*)(Ag + (size_t)(i * 32) * KDIM + k0);
#pragma unroll
        for (int i = 0; i < 4; i++)
            bufB[i] = *(const float4*)(Wg + (size_t)(k0 + i * 8) * N);
    };

    auto sts_chunk = [&](int s) {
        float* sa = smem + s * STG_FLOATS;
        float* sb = sa + A_STG;
#pragma unroll
        for (int i = 0; i < 4; i++) {
            uint4 v;
            v.x = f2tf32(bufA[i].x); v.y = f2tf32(bufA[i].y);
            v.z = f2tf32(bufA[i].z); v.w = f2tf32(bufA[i].w);
            *(uint4*)(sa + (ar + i * 32) * AS + ac4 * 4) = v;
        }
#pragma unroll
        for (int i = 0; i < 4; i++) {
            uint4 v;
            v.x = f2tf32(bufB[i].x); v.y = f2tf32(bufB[i].y);
            v.z = f2tf32(bufB[i].z); v.w = f2tf32(bufB[i].w);
            *(uint4*)(sb + (bk + i * 8) * BS + bc4 * 4) = v;
        }
    };

    float acc[2][8][4];
#pragma unroll
    for (int m = 0; m < 2; m++)
#pragma unroll
        for (int n = 0; n < 8; n++)
#pragma unroll
            for (int c = 0; c < 4; c++) acc[m][n][c] = 0.f;

    ldg_chunk(0);
    sts_chunk(0);
    __syncthreads();

    const int rb0 = wm * 32 + grp;       // A row for a0/a2
    const int cb0 = wn * 64 + grp;       // B col base + n*8

    for (int j = 0; j < NT; j++) {
        if (j + 1 < NT) ldg_chunk(j + 1);

        const float* sa = smem + (j & 1) * STG_FLOATS;
        const float* sb = sa + A_STG;
#pragma unroll
        for (int ks = 0; ks < 4; ks++) {
            int kc = ks * 8 + tig;
            uint32_t af[2][4];
#pragma unroll
            for (int m = 0; m < 2; m++) {
                const float* ap = sa + (rb0 + m * 16) * AS + kc;
                af[m][0] = __float_as_uint(ap[0]);
                af[m][1] = __float_as_uint(ap[8 * AS]);
                af[m][2] = __float_as_uint(ap[4]);
                af[m][3] = __float_as_uint(ap[8 * AS + 4]);
            }
            uint32_t bf[8][2];
            const float* bp = sb + kc * BS + cb0;
#pragma unroll
            for (int n = 0; n < 8; n++) {
                bf[n][0] = __float_as_uint(bp[n * 8]);
                bf[n][1] = __float_as_uint(bp[4 * BS + n * 8]);
            }
#pragma unroll
            for (int m = 0; m < 2; m++)
#pragma unroll
                for (int n = 0; n < 8; n++)
                    mma_tf32(acc[m][n][0], acc[m][n][1], acc[m][n][2], acc[m][n][3],
                             af[m][0], af[m][1], af[m][2], af[m][3],
                             bf[n][0], bf[n][1]);
        }

        if (j + 1 < NT) sts_chunk((j + 1) & 1);
        __syncthreads();
    }

    // Epilogue
#pragma unroll
    for (int m = 0; m < 2; m++) {
        int row0 = brow * 128 + wm * 32 + m * 16 + grp;
#pragma unroll
        for (int n = 0; n < 8; n++) {
            int col = bcol * 128 + wn * 64 + n * 8 + tig * 2;
            float2 bv = *(const float2*)(bias + col);
            float2 o0, o1;
            o0.x = acc[m][n][0] + bv.x; o0.y = acc[m][n][1] + bv.y;
            o1.x = acc[m][n][2] + bv.x; o1.y = acc[m][n][3] + bv.y;
            *(float2*)(C + (size_t)row0 * N + col)       = o0;
            *(float2*)(C + (size_t)(row0 + 8) * N + col) = o1;
        }
    }
}

// ===========================================================================
// RoPE
// ===========================================================================
__global__ void rope_table_kernel() {
    int idx = blockIdx.x * blockDim.x + threadIdx.x;
    if (idx >= SEQ * 64) return;
    int s = idx >> 6;
    int i = idx & 63;
    double theta = exp(-(double)i * log(10000.0) / 64.0);
    float tf = (float)theta;
    float ang = (float)s * tf;
    g_cos[idx] = (float)cos((double)ang);
    g_sin[idx] = (float)sin((double)ang);
}

__global__ void rope_apply_kernel() {
    int idx = blockIdx.x * blockDim.x + threadIdx.x;
    int i = idx & 63;
    int h = (idx >> 6) & (NHEAD - 1);
    int s = (idx >> 10) & (SEQ - 1);
    int b = idx >> 21;
    if (b >= BATCH) return;

    float c  = g_cos[s * 64 + i];
    float sn = g_sin[s * 64 + i];

    size_t base = ((size_t)(b * SEQ + s)) * D3 + h * DHEAD;
    float* q = g_qkv + base;
    float* k = g_qkv + base + DMODEL;

    float q0 = q[i], q1 = q[i + 64];
    q[i]      = c * q0 - sn * q1;
    q[i + 64] = c * q1 + sn * q0;

    float k0 = k[i], k1 = k[i + 64];
    k[i]      = c * k0 - sn * k1;
    k[i + 64] = c * k1 + sn * k0;
}

// ===========================================================================
// Flash attention fp32 — parallel row reductions (shfl), prescaled Q.
// 1 CTA/SM (smem-limited anyway); regs free to 168.
// ===========================================================================
#define ATT_SMEM_FLOATS (128*65 + 128*65 + 64*128 + 64*65 + 3*64)

__global__ __launch_bounds__(256, 1)
void attn_kernel(const float* __restrict__ qkv, float* __restrict__ out) {
    extern __shared__ float sm[];
    float* Qs = sm;                    // [128][65]  d-major, pre-scaled
    float* Ks = Qs + 128 * 65;         // [128][65]
    float* Vs = Ks + 128 * 65;         // [64][128]
    float* Ps = Vs + 64 * 128;         // [64][65]
    float* sh_m     = Ps + 64 * 65;
    float* sh_alpha = sh_m + 64;
    float* sh_l     = sh_alpha + 64;

    const float SCALE = 0.08838834764831845f;  // 1/sqrt(128)
    const float NEG_BIG = -3.0e38f;

    int qt = blockIdx.x;
    int h  = blockIdx.y;
    int b  = blockIdx.z;
    int tid = threadIdx.x;
    int tx = tid & 15;
    int ty = tid >> 4;
    int rid = tid >> 2;    // row for reduction passes (0..63)
    int rq  = tid & 3;     // 4 lanes per row

    const float* qbase = qkv + ((size_t)(b * SEQ)) * D3 + h * DHEAD;
    const float* kbase = qbase + DMODEL;
    const float* vbase = qbase + 2 * DMODEL;

    int qrow0 = qt * 64;

#pragma unroll
    for (int t = 0; t < 8; t++) {
        int lin = tid + t * 256;
        int row = lin >> 5;
        int d0 = (lin & 31) * 4;
        float4 v = *(const float4*)(qbase + (size_t)(qrow0 + row) * D3 + d0);
        Qs[(d0 + 0) * 65 + row] = v.x * SCALE;
        Qs[(d0 + 1) * 65 + row] = v.y * SCALE;
        Qs[(d0 + 2) * 65 + row] = v.z * SCALE;
        Qs[(d0 + 3) * 65 + row] = v.w * SCALE;
    }
    if (tid < 64) { sh_m[tid] = NEG_BIG; sh_l[tid] = 0.f; }

    float O[4][8];
#pragma unroll
    for (int i = 0; i < 4; i++)
#pragma unroll
        for (int j = 0; j < 8; j++) O[i][j] = 0.f;

    for (int kt = 0; kt <= qt; kt++) {
        __syncthreads();

#pragma unroll
        for (int t = 0; t < 8; t++) {
            int lin = tid + t * 256;
            int row = lin >> 5;
            int d0 = (lin & 31) * 4;
            size_t goff = (size_t)(kt * 64 + row) * D3 + d0;
            float4 kv = *(const float4*)(kbase + goff);
            Ks[(d0 + 0) * 65 + row] = kv.x;
            Ks[(d0 + 1) * 65 + row] = kv.y;
            Ks[(d0 + 2) * 65 + row] = kv.z;
            Ks[(d0 + 3) * 65 + row] = kv.w;
            float4 vv = *(const float4*)(vbase + goff);
            *(float4*)(Vs + row * 128 + d0) = vv;
        }
        __syncthreads();

        float accS[4][4];
#pragma unroll
        for (int i = 0; i < 4; i++)
#pragma unroll
            for (int j = 0; j < 4; j++) accS[i][j] = 0.f;

#pragma unroll 4
        for (int d = 0; d < 128; d++) {
            float qr[4], kr[4];
#pragma unroll
            for (int i = 0; i < 4; i++) qr[i] = Qs[d * 65 + ty * 4 + i];
#pragma unroll
            for (int j = 0; j < 4; j++) kr[j] = Ks[d * 65 + tx * 4 + j];
#pragma unroll
            for (int i = 0; i < 4; i++)
#pragma unroll
                for (int j = 0; j < 4; j++) accS[i][j] += qr[i] * kr[j];
        }
#pragma unroll
        for (int i = 0; i < 4; i++)
#pragma unroll
            for (int j = 0; j < 4; j++)
                Ps[(ty * 4 + i) * 65 + tx * 4 + j] = accS[i][j];
        __syncthreads();

        // Parallel row max (4 lanes/row, causal on the fly)
        {
            int limit = (kt == qt) ? rid : 63;
            float mt = NEG_BIG;
#pragma unroll
            for (int c0 = 0; c0 < 16; c0++) {
                int c = rq * 16 + c0;
                float v = Ps[rid * 65 + c];
                if (c <= limit) mt = fmaxf(mt, v);
            }
            mt = fmaxf(mt, __shfl_xor_sync(0xFFFFFFFF, mt, 1));
            mt = fmaxf(mt, __shfl_xor_sync(0xFFFFFFFF, mt, 2));
            if (rq == 0) {
                float mo = sh_m[rid];
                float mn = fmaxf(mo, mt);
                sh_m[rid] = mn;
                sh_alpha[rid] = __expf(mo - mn);
            }
        }
        __syncthreads();

        // Rescale O; exponentiate with causal mask
#pragma unroll
        for (int i = 0; i < 4; i++) {
            float a = sh_alpha[ty * 4 + i];
#pragma unroll
            for (int j = 0; j < 8; j++) O[i][j] *= a;
        }
#pragma unroll
        for (int i = 0; i < 4; i++) {
            int r = ty * 4 + i;
            int limit = (kt == qt) ? r : 63;
            float mn = sh_m[r];
#pragma unroll
            for (int j = 0; j < 4; j++) {
                int c = tx * 4 + j;
                float p = (c <= limit) ? __expf(Ps[r * 65 + c] - mn) : 0.f;
                Ps[r * 65 + c] = p;
            }
        }
        __syncthreads();

        // Parallel row sum
        {
            float s = 0.f;
#pragma unroll
            for (int c0 = 0; c0 < 16; c0++)
                s += Ps[rid * 65 + rq * 16 + c0];
            s += __shfl_xor_sync(0xFFFFFFFF, s, 1);
            s += __shfl_xor_sync(0xFFFFFFFF, s, 2);
            if (rq == 0)
                sh_l[rid] = sh_l[rid] * sh_alpha[rid] + s;
        }

        // O += P @ V
#pragma unroll 2
        for (int k = 0; k < 64; k++) {
            float pr[4];
#pragma unroll
            for (int i = 0; i < 4; i++) pr[i] = Ps[(ty * 4 + i) * 65 + k];
            float vr[8];
            *(float4*)(vr)     = *(float4*)(Vs + k * 128 + tx * 8);
            *(float4*)(vr + 4) = *(float4*)(Vs + k * 128 + tx * 8 + 4);
#pragma unroll
            for (int i = 0; i < 4; i++)
#pragma unroll
                for (int j = 0; j < 8; j++) O[i][j] += pr[i] * vr[j];
        }
    }
    __syncthreads();

#pragma unroll
    for (int i = 0; i < 4; i++) {
        int r = ty * 4 + i;
        float inv = 1.f / sh_l[r];
        int qg = qrow0 + r;
        float o[8];
#pragma unroll
        for (int j = 0; j < 8; j++) o[j] = O[i][j] * inv;
        float* dst = out + ((size_t)(b * SEQ + qg)) * DMODEL + h * DHEAD + tx * 8;
        *(float4*)(dst)     = *(float4*)(o);
        *(float4*)(dst + 4) = *(float4*)(o + 4);
    }
}

// ===========================================================================
// Launch
// ===========================================================================
extern "C" void kernel_launch(void* const* d_in, const int* in_sizes, int n_in,
                              void* d_out, int out_size) {
    const float* x     = (const float*)d_in[0];
    const float* w_in  = (const float*)d_in[2];
    const float* b_in  = (const float*)d_in[3];
    const float* w_out = (const float*)d_in[4];
    const float* b_out = (const float*)d_in[5];
    float* out = (float*)d_out;

    float* qkv;   cudaGetSymbolAddress((void**)&qkv,  g_qkv);
    float* attn;  cudaGetSymbolAddress((void**)&attn, g_attn);

    cudaFuncSetAttribute(attn_kernel,
                         cudaFuncAttributeMaxDynamicSharedMemorySize,
                         ATT_SMEM_FLOATS * (int)sizeof(float));
    cudaFuncSetAttribute(mma_gemm_kernel,
                         cudaFuncAttributeMaxDynamicSharedMemorySize,
                         GEMM_SMEM);

    // 1. RoPE tables
    rope_table_kernel<<<(SEQ * 64 + 255) / 256, 256>>>();

    // 2. QKV projection (mma.sync tf32)
    mma_gemm_kernel<<<dim3(D3 / 128, (BATCH * SEQ) / 128), 256, GEMM_SMEM>>>(
        x, w_in, b_in, qkv, D3);

    // 3. RoPE in-place on q,k
    rope_apply_kernel<<<(BATCH * SEQ * NHEAD * 64) / 256, 256>>>();

    // 4. Flash attention
    attn_kernel<<<dim3(SEQ / 64, NHEAD, BATCH), 256,
                  ATT_SMEM_FLOATS * sizeof(float)>>>(qkv, attn);

    // 5. Output projection (mma.sync tf32)
    mma_gemm_kernel<<<dim3(DMODEL / 128, (BATCH * SEQ) / 128), 256, GEMM_SMEM>>>(
        attn, w_out, b_out, out, DMODEL);
}

// round 7
// speedup vs baseline: 3.0940x; 1.6585x over previous
#include <cuda_runtime.h>
#include <math.h>
#include <stdint.h>

#define BATCH 2
#define SEQ   2048
#define DMODEL 2048
#define NHEAD 16
#define DHEAD 128
#define D3    (3*DMODEL)
#define KDIM  2048

// Scratch (device globals — no allocation allowed)
__device__ float g_qkv[(size_t)BATCH * SEQ * D3];        // [B,S,3D]
__device__ float g_attn[(size_t)BATCH * SEQ * DMODEL];   // [B,S,D]
__device__ float g_cos[SEQ * 64];
__device__ float g_sin[SEQ * 64];

__device__ __forceinline__ uint32_t f2tf32(float x) {
    uint32_t r;
    asm("cvt.rna.tf32.f32 %0, %1;" : "=r"(r) : "f"(x));
    return r;
}
__device__ __forceinline__ float tf32r(float x) {
    float r;
    asm("cvt.rna.tf32.f32 %0, %1;" : "=f"(r) : "f"(x));
    return r;
}

__device__ __forceinline__ void mma_tf32(float& d0, float& d1, float& d2, float& d3,
                                         uint32_t a0, uint32_t a1, uint32_t a2, uint32_t a3,
                                         uint32_t b0, uint32_t b1) {
    asm volatile(
        "mma.sync.aligned.m16n8k8.row.col.f32.tf32.tf32.f32 "
        "{%0,%1,%2,%3}, {%4,%5,%6,%7}, {%8,%9}, {%0,%1,%2,%3};"
        : "+f"(d0), "+f"(d1), "+f"(d2), "+f"(d3)
        : "r"(a0), "r"(a1), "r"(a2), "r"(a3), "r"(b0), "r"(b1));
}

// ===========================================================================
// mma.sync tf32 GEMM (unchanged from round 6 — known good)
// ===========================================================================
#define BK 32
#define NT (KDIM / BK)
#define AS 36
#define BS 136
#define A_STG (128 * AS)
#define B_STG (32 * BS)
#define STG_FLOATS (A_STG + B_STG)
#define GEMM_SMEM (2 * STG_FLOATS * 4)

__global__ void __launch_bounds__(256, 1)
mma_gemm_kernel(const float* __restrict__ A, const float* __restrict__ W,
                const float* __restrict__ bias, float* __restrict__ C, int N) {
    extern __shared__ float smem[];

    const int tid  = threadIdx.x;
    const int lane = tid & 31;
    const int warp = tid >> 5;
    const int wm   = warp >> 1;
    const int wn   = warp & 1;
    const int grp  = lane >> 2;
    const int tig  = lane & 3;
    const int brow = blockIdx.y;
    const int bcol = blockIdx.x;

    const int ar  = tid >> 3;
    const int ac4 = tid & 7;
    const int bk  = tid >> 5;
    const int bc4 = tid & 31;

    const float* Ag = A + (size_t)(brow * 128 + ar) * KDIM + ac4 * 4;
    const float* Wg = W + (size_t)bk * N + bcol * 128 + bc4 * 4;

    float4 bufA[4], bufB[4];

    auto ldg_chunk = [&](int j) {
        int k0 = j * BK;
#pragma unroll
        for (int i = 0; i < 4; i++)
            bufA[i] = *(const float4*)(Ag + (size_t)(i * 32) * KDIM + k0);
#pragma unroll
        for (int i = 0; i < 4; i++)
            bufB[i] = *(const float4*)(Wg + (size_t)(k0 + i * 8) * N);
    };

    auto sts_chunk = [&](int s) {
        float* sa = smem + s * STG_FLOATS;
        float* sb = sa + A_STG;
#pragma unroll
        for (int i = 0; i < 4; i++) {
            uint4 v;
            v.x = f2tf32(bufA[i].x); v.y = f2tf32(bufA[i].y);
            v.z = f2tf32(bufA[i].z); v.w = f2tf32(bufA[i].w);
            *(uint4*)(sa + (ar + i * 32) * AS + ac4 * 4) = v;
        }
#pragma unroll
        for (int i = 0; i < 4; i++) {
            uint4 v;
            v.x = f2tf32(bufB[i].x); v.y = f2tf32(bufB[i].y);
            v.z = f2tf32(bufB[i].z); v.w = f2tf32(bufB[i].w);
            *(uint4*)(sb + (bk + i * 8) * BS + bc4 * 4) = v;
        }
    };

    float acc[2][8][4];
#pragma unroll
    for (int m = 0; m < 2; m++)
#pragma unroll
        for (int n = 0; n < 8; n++)
#pragma unroll
            for (int c = 0; c < 4; c++) acc[m][n][c] = 0.f;

    ldg_chunk(0);
    sts_chunk(0);
    __syncthreads();

    const int rb0 = wm * 32 + grp;
    const int cb0 = wn * 64 + grp;

    for (int j = 0; j < NT; j++) {
        if (j + 1 < NT) ldg_chunk(j + 1);

        const float* sa = smem + (j & 1) * STG_FLOATS;
        const float* sb = sa + A_STG;
#pragma unroll
        for (int ks = 0; ks < 4; ks++) {
            int kc = ks * 8 + tig;
            uint32_t af[2][4];
#pragma unroll
            for (int m = 0; m < 2; m++) {
                const float* ap = sa + (rb0 + m * 16) * AS + kc;
                af[m][0] = __float_as_uint(ap[0]);
                af[m][1] = __float_as_uint(ap[8 * AS]);
                af[m][2] = __float_as_uint(ap[4]);
                af[m][3] = __float_as_uint(ap[8 * AS + 4]);
            }
            uint32_t bf[8][2];
            const float* bp = sb + kc * BS + cb0;
#pragma unroll
            for (int n = 0; n < 8; n++) {
                bf[n][0] = __float_as_uint(bp[n * 8]);
                bf[n][1] = __float_as_uint(bp[4 * BS + n * 8]);
            }
#pragma unroll
            for (int m = 0; m < 2; m++)
#pragma unroll
                for (int n = 0; n < 8; n++)
                    mma_tf32(acc[m][n][0], acc[m][n][1], acc[m][n][2], acc[m][n][3],
                             af[m][0], af[m][1], af[m][2], af[m][3],
                             bf[n][0], bf[n][1]);
        }

        if (j + 1 < NT) sts_chunk((j + 1) & 1);
        __syncthreads();
    }

#pragma unroll
    for (int m = 0; m < 2; m++) {
        int row0 = brow * 128 + wm * 32 + m * 16 + grp;
#pragma unroll
        for (int n = 0; n < 8; n++) {
            int col = bcol * 128 + wn * 64 + n * 8 + tig * 2;
            float2 bv = *(const float2*)(bias + col);
            float2 o0, o1;
            o0.x = acc[m][n][0] + bv.x; o0.y = acc[m][n][1] + bv.y;
            o1.x = acc[m][n][2] + bv.x; o1.y = acc[m][n][3] + bv.y;
            *(float2*)(C + (size_t)row0 * N + col)       = o0;
            *(float2*)(C + (size_t)(row0 + 8) * N + col) = o1;
        }
    }
}

// ===========================================================================
// RoPE
// ===========================================================================
__global__ void rope_table_kernel() {
    int idx = blockIdx.x * blockDim.x + threadIdx.x;
    if (idx >= SEQ * 64) return;
    int s = idx >> 6;
    int i = idx & 63;
    double theta = exp(-(double)i * log(10000.0) / 64.0);
    float tf = (float)theta;
    float ang = (float)s * tf;
    g_cos[idx] = (float)cos((double)ang);
    g_sin[idx] = (float)sin((double)ang);
}

__global__ void rope_apply_kernel() {
    int idx = blockIdx.x * blockDim.x + threadIdx.x;
    int i = idx & 63;
    int h = (idx >> 6) & (NHEAD - 1);
    int s = (idx >> 10) & (SEQ - 1);
    int b = idx >> 21;
    if (b >= BATCH) return;

    float c  = g_cos[s * 64 + i];
    float sn = g_sin[s * 64 + i];

    size_t base = ((size_t)(b * SEQ + s)) * D3 + h * DHEAD;
    float* q = g_qkv + base;
    float* k = g_qkv + base + DMODEL;

    float q0 = q[i], q1 = q[i + 64];
    q[i]      = c * q0 - sn * q1;
    q[i + 64] = c * q1 + sn * q0;

    float k0 = k[i], k1 = k[i + 64];
    k[i]      = c * k0 - sn * k1;
    k[i + 64] = c * k1 + sn * k0;
}

// ===========================================================================
// Flash attention on mma.sync tf32.
// CTA: 64 q-rows, kv-tile 128, 256 threads (8 warps).
// Warp w: q-group (w&3) -> rows (w&3)*16 + {grp, grp+8};  half (w>>2):
//   QK: key-half; PV: d-half.
// Smem pads: Q/K/P = 132 (bank 4*grp+tig, conflict-free), V = 136 (8*tig+grp).
// ===========================================================================
#define QS_PAD 132
#define KS_PAD 132
#define VS_PAD 136
#define PS_PAD 132
#define QS_OFF 0
#define KS_OFF (64 * QS_PAD)                 // 8448
#define VS_OFF (KS_OFF + 128 * KS_PAD)       // 25344
#define PS_OFF (VS_OFF + 128 * VS_PAD)       // 42752
#define PM_OFF (PS_OFF + 64 * PS_PAD)        // 51200
#define PL_OFF (PM_OFF + 128)                // 51328
#define ATT_SMEM_FLOATS (PL_OFF + 128)       // 51456 floats = 205824 B

__global__ void __launch_bounds__(256, 1)
attn_mma_kernel(const float* __restrict__ qkv, float* __restrict__ out) {
    extern __shared__ float sm[];
    float* Qs = sm + QS_OFF;
    float* Ks = sm + KS_OFF;
    float* Vs = sm + VS_OFF;
    float* Ps = sm + PS_OFF;
    float* pm = sm + PM_OFF;   // [2][64]
    float* pl = sm + PL_OFF;   // [2][64]

    const float SCALE = 0.08838834764831845f;  // 1/sqrt(128)
    const float NEG_BIG = -3.0e38f;

    const int qt = blockIdx.x, h = blockIdx.y, b = blockIdx.z;
    const int tid = threadIdx.x;
    const int lane = tid & 31, warp = tid >> 5;
    const int grp = lane >> 2, tig = lane & 3;
    const int qg = warp & 3, half = warp >> 2;
    const int n0 = half * 64;

    const float* qbase = qkv + (size_t)(b * SEQ) * D3 + h * DHEAD;
    const float* kbase = qbase + DMODEL;
    const float* vbase = qbase + 2 * DMODEL;

    const int qrow0 = qt * 64;
    const int r_lo = qg * 16 + grp;
    const int r_hi = r_lo + 8;

    // Load Q once: prescaled + tf32-rounded
#pragma unroll
    for (int t = 0; t < 8; t++) {
        int lin = tid + t * 256;
        int row = lin >> 5;
        int d0 = (lin & 31) * 4;
        float4 v = *(const float4*)(qbase + (size_t)(qrow0 + row) * D3 + d0);
        float4 o;
        o.x = tf32r(v.x * SCALE); o.y = tf32r(v.y * SCALE);
        o.z = tf32r(v.z * SCALE); o.w = tf32r(v.w * SCALE);
        *(float4*)(Qs + row * QS_PAD + d0) = o;
    }

    float oacc[8][4];
#pragma unroll
    for (int j = 0; j < 8; j++)
#pragma unroll
        for (int c = 0; c < 4; c++) oacc[j][c] = 0.f;

    float m_lo = NEG_BIG, m_hi = NEG_BIG;
    float l_lo = 0.f, l_hi = 0.f;

    const int nkt = (qt >> 1) + 1;

    for (int kt = 0; kt < nkt; kt++) {
        const int key0 = kt * 128;
        const int doff = qt * 64 - key0;

        __syncthreads();   // prev iteration's Ps/Vs reads done; Q visible (kt=0)

        // Load K,V tile [128][128] (tf32-rounded)
#pragma unroll
        for (int t = 0; t < 16; t++) {
            int lin = tid + t * 256;
            int row = lin >> 5;
            int d0 = (lin & 31) * 4;
            size_t goff = (size_t)(key0 + row) * D3 + d0;
            float4 kv = *(const float4*)(kbase + goff);
            float4 ko;
            ko.x = tf32r(kv.x); ko.y = tf32r(kv.y);
            ko.z = tf32r(kv.z); ko.w = tf32r(kv.w);
            *(float4*)(Ks + row * KS_PAD + d0) = ko;
            float4 vv = *(const float4*)(vbase + goff);
            float4 vo;
            vo.x = tf32r(vv.x); vo.y = tf32r(vv.y);
            vo.z = tf32r(vv.z); vo.w = tf32r(vv.w);
            *(float4*)(Vs + row * VS_PAD + d0) = vo;
        }
        __syncthreads();

        // ---- S = Q @ K^T on this warp's key half ----
        float sacc[8][4];
#pragma unroll
        for (int j = 0; j < 8; j++)
#pragma unroll
            for (int c = 0; c < 4; c++) sacc[j][c] = 0.f;

        const float* qpA = Qs + r_lo * QS_PAD;
        const float* kpB = Ks + (n0 + grp) * KS_PAD;
#pragma unroll 4
        for (int ks = 0; ks < 16; ks++) {
            int kc = ks * 8 + tig;
            uint32_t a0 = __float_as_uint(qpA[kc]);
            uint32_t a1 = __float_as_uint(qpA[8 * QS_PAD + kc]);
            uint32_t a2 = __float_as_uint(qpA[kc + 4]);
            uint32_t a3 = __float_as_uint(qpA[8 * QS_PAD + kc + 4]);
#pragma unroll
            for (int j = 0; j < 8; j++) {
                uint32_t b0 = __float_as_uint(kpB[j * 8 * KS_PAD + kc]);
                uint32_t b1 = __float_as_uint(kpB[j * 8 * KS_PAD + kc + 4]);
                mma_tf32(sacc[j][0], sacc[j][1], sacc[j][2], sacc[j][3],
                         a0, a1, a2, a3, b0, b1);
            }
        }

        // ---- partial row max (causal mask via predicate) ----
        float pmax_lo = NEG_BIG, pmax_hi = NEG_BIG;
#pragma unroll
        for (int j = 0; j < 8; j++) {
            int c0 = n0 + j * 8 + 2 * tig;
            if (c0     <= r_lo + doff) pmax_lo = fmaxf(pmax_lo, sacc[j][0]);
            if (c0 + 1 <= r_lo + doff) pmax_lo = fmaxf(pmax_lo, sacc[j][1]);
            if (c0     <= r_hi + doff) pmax_hi = fmaxf(pmax_hi, sacc[j][2]);
            if (c0 + 1 <= r_hi + doff) pmax_hi = fmaxf(pmax_hi, sacc[j][3]);
        }
        pmax_lo = fmaxf(pmax_lo, __shfl_xor_sync(0xFFFFFFFF, pmax_lo, 1));
        pmax_lo = fmaxf(pmax_lo, __shfl_xor_sync(0xFFFFFFFF, pmax_lo, 2));
        pmax_hi = fmaxf(pmax_hi, __shfl_xor_sync(0xFFFFFFFF, pmax_hi, 1));
        pmax_hi = fmaxf(pmax_hi, __shfl_xor_sync(0xFFFFFFFF, pmax_hi, 2));
        if (tig == 0) {
            pm[half * 64 + r_lo] = pmax_lo;
            pm[half * 64 + r_hi] = pmax_hi;
        }
        __syncthreads();

        // ---- combine halves, exp, partial sums, store P ----
        float mn_lo = fmaxf(m_lo, fmaxf(pm[r_lo], pm[64 + r_lo]));
        float mn_hi = fmaxf(m_hi, fmaxf(pm[r_hi], pm[64 + r_hi]));
        float al_lo = __expf(m_lo - mn_lo);
        float al_hi = __expf(m_hi - mn_hi);
        m_lo = mn_lo; m_hi = mn_hi;

        float sum_lo = 0.f, sum_hi = 0.f;
#pragma unroll
        for (int j = 0; j < 8; j++) {
            int c0 = n0 + j * 8 + 2 * tig;
            float p0 = (c0     <= r_lo + doff) ? __expf(sacc[j][0] - mn_lo) : 0.f;
            float p1 = (c0 + 1 <= r_lo + doff) ? __expf(sacc[j][1] - mn_lo) : 0.f;
            float p2 = (c0     <= r_hi + doff) ? __expf(sacc[j][2] - mn_hi) : 0.f;
            float p3 = (c0 + 1 <= r_hi + doff) ? __expf(sacc[j][3] - mn_hi) : 0.f;
            sum_lo += p0 + p1;
            sum_hi += p2 + p3;
            float2 v01; v01.x = tf32r(p0); v01.y = tf32r(p1);
            float2 v23; v23.x = tf32r(p2); v23.y = tf32r(p3);
            *(float2*)(Ps + r_lo * PS_PAD + c0) = v01;
            *(float2*)(Ps + r_hi * PS_PAD + c0) = v23;
        }
        sum_lo += __shfl_xor_sync(0xFFFFFFFF, sum_lo, 1);
        sum_lo += __shfl_xor_sync(0xFFFFFFFF, sum_lo, 2);
        sum_hi += __shfl_xor_sync(0xFFFFFFFF, sum_hi, 1);
        sum_hi += __shfl_xor_sync(0xFFFFFFFF, sum_hi, 2);
        if (tig == 0) {
            pl[half * 64 + r_lo] = sum_lo;
            pl[half * 64 + r_hi] = sum_hi;
        }
        __syncthreads();

        // ---- l update, O rescale, PV mma on this warp's d half ----
        l_lo = l_lo * al_lo + pl[r_lo] + pl[64 + r_lo];
        l_hi = l_hi * al_hi + pl[r_hi] + pl[64 + r_hi];
#pragma unroll
        for (int j = 0; j < 8; j++) {
            oacc[j][0] *= al_lo; oacc[j][1] *= al_lo;
            oacc[j][2] *= al_hi; oacc[j][3] *= al_hi;
        }

        const float* ppA = Ps + r_lo * PS_PAD;
#pragma unroll 4
        for (int ks = 0; ks < 16; ks++) {
            int kc = ks * 8 + tig;
            uint32_t a0 = __float_as_uint(ppA[kc]);
            uint32_t a1 = __float_as_uint(ppA[8 * PS_PAD + kc]);
            uint32_t a2 = __float_as_uint(ppA[kc + 4]);
            uint32_t a3 = __float_as_uint(ppA[8 * PS_PAD + kc + 4]);
            const float* vpB = Vs + kc * VS_PAD + n0 + grp;
#pragma unroll
            for (int j = 0; j < 8; j++) {
                uint32_t b0 = __float_as_uint(vpB[j * 8]);
                uint32_t b1 = __float_as_uint(vpB[4 * VS_PAD + j * 8]);
                mma_tf32(oacc[j][0], oacc[j][1], oacc[j][2], oacc[j][3],
                         a0, a1, a2, a3, b0, b1);
            }
        }
    }

    // ---- normalize + store ----
    float inv_lo = 1.f / l_lo;
    float inv_hi = 1.f / l_hi;
    float* obase = out + (size_t)(b * SEQ + qrow0) * DMODEL + h * DHEAD;
#pragma unroll
    for (int j = 0; j < 8; j++) {
        int col = n0 + j * 8 + 2 * tig;
        float2 o0, o1;
        o0.x = oacc[j][0] * inv_lo; o0.y = oacc[j][1] * inv_lo;
        o1.x = oacc[j][2] * inv_hi; o1.y = oacc[j][3] * inv_hi;
        *(float2*)(obase + (size_t)r_lo * DMODEL + col) = o0;
        *(float2*)(obase + (size_t)r_hi * DMODEL + col) = o1;
    }
}

// ===========================================================================
// Launch
// ===========================================================================
extern "C" void kernel_launch(void* const* d_in, const int* in_sizes, int n_in,
                              void* d_out, int out_size) {
    const float* x     = (const float*)d_in[0];
    const float* w_in  = (const float*)d_in[2];
    const float* b_in  = (const float*)d_in[3];
    const float* w_out = (const float*)d_in[4];
    const float* b_out = (const float*)d_in[5];
    float* out = (float*)d_out;

    float* qkv;   cudaGetSymbolAddress((void**)&qkv,  g_qkv);
    float* attn;  cudaGetSymbolAddress((void**)&attn, g_attn);

    cudaFuncSetAttribute(attn_mma_kernel,
                         cudaFuncAttributeMaxDynamicSharedMemorySize,
                         ATT_SMEM_FLOATS * (int)sizeof(float));
    cudaFuncSetAttribute(mma_gemm_kernel,
                         cudaFuncAttributeMaxDynamicSharedMemorySize,
                         GEMM_SMEM);

    // 1. RoPE tables
    rope_table_kernel<<<(SEQ * 64 + 255) / 256, 256>>>();

    // 2. QKV projection (mma.sync tf32)
    mma_gemm_kernel<<<dim3(D3 / 128, (BATCH * SEQ) / 128), 256, GEMM_SMEM>>>(
        x, w_in, b_in, qkv, D3);

    // 3. RoPE in-place on q,k
    rope_apply_kernel<<<(BATCH * SEQ * NHEAD * 64) / 256, 256>>>();

    // 4. Flash attention (mma.sync tf32)
    attn_mma_kernel<<<dim3(SEQ / 64, NHEAD, BATCH), 256,
                      ATT_SMEM_FLOATS * sizeof(float)>>>(qkv, attn);

    // 5. Output projection (mma.sync tf32)
    mma_gemm_kernel<<<dim3(DMODEL / 128, (BATCH * SEQ) / 128), 256, GEMM_SMEM>>>(
        attn, w_out, b_out, out, DMODEL);
}